// round 3
// baseline (speedup 1.0000x reference)
#include <cuda_runtime.h>

// Fixed-shape problem: logits [8,19,512,512] f32, target [8,512,512] (int32 on device)
#define NCLS 19
#define HW   262144           // 512*512
#define CHW  (NCLS * HW)
#define NBLK 592              // 4 blocks/SM * 148 SMs
#define NTHR 256

// Per-block partials: [0..18]=prob_sums, [19..37]=intersection, [38..56]=counts,
// [57]=sum w_t, [58]=sum w_t*log_pt, [59]=sum alpha*(1-pt)^2*log_pt
__device__ float    g_part[NBLK][64];
__device__ unsigned g_sem;     // zero-initialized; self-resetting

__device__ __forceinline__ float ex2f(float x){ float r; asm("ex2.approx.ftz.f32 %0,%1;":"=f"(r):"f"(x)); return r; }
__device__ __forceinline__ float lg2f(float x){ float r; asm("lg2.approx.ftz.f32 %0,%1;":"=f"(r):"f"(x)); return r; }
__device__ __forceinline__ float rcpf(float x){ float r; asm("rcp.approx.ftz.f32 %0,%1;":"=f"(r):"f"(x)); return r; }

__global__ void __launch_bounds__(NTHR, 2)
fdl_kernel(const float* __restrict__ logits,
           const int*   __restrict__ target,
           const float* __restrict__ cw,
           const float* __restrict__ fa,
           float*       __restrict__ out,
           int P)
{
    __shared__ float s_cw[NCLS], s_fa[NCLS];
    __shared__ float s_red[64];
    __shared__ float s_fin[4][64];
    __shared__ bool  s_last;

    const int tid = threadIdx.x;
    if (tid < NCLS) { s_cw[tid] = cw[tid]; s_fa[tid] = fa[tid]; }
    if (tid < 64)   s_red[tid] = 0.f;
    __syncthreads();

    // Per-thread accumulators (fully register-resident, unrolled indexing only)
    float ps[NCLS], inter[NCLS];
    int   cnt[NCLS];
#pragma unroll
    for (int c = 0; c < NCLS; ++c) { ps[c] = 0.f; inter[c] = 0.f; cnt[c] = 0; }
    float aw = 0.f, anll = 0.f, afoc = 0.f;

    const int stride = NBLK * NTHR;
    for (int pix = blockIdx.x * NTHR + tid; pix < P; pix += stride) {
        const int b  = pix >> 18;              // pix / HW
        const int hw = pix & (HW - 1);
        const float* base = logits + (size_t)b * CHW + hw;
        const int t = target[pix];

        // 19 coalesced class streams; convert to log2 domain at load
        float y[NCLS];
#pragma unroll
        for (int c = 0; c < NCLS; ++c)
            y[c] = __ldg(base + (size_t)c * HW) * 1.44269504089f;

        // gather y[t] via select chain (no dynamic register indexing)
        float yt = y[0];
#pragma unroll
        for (int c = 1; c < NCLS; ++c) yt = (t == c) ? y[c] : yt;

        // softmax pieces (no max-shift: |logit| small, 2^y can't overflow)
        float e[NCLS];
        float S = 0.f;
#pragma unroll
        for (int c = 0; c < NCLS; ++c) { e[c] = ex2f(y[c]); S += e[c]; }
        const float invS = rcpf(S);
        const float d    = yt - lg2f(S);       // log2(p_t)
        const float log_pt = d * 0.69314718056f;
        const float pt     = ex2f(d);

        const float wt = s_cw[t];
        const float at = s_fa[t];
        aw   += wt;
        anll  = fmaf(wt, log_pt, anll);                    // negate at end
        const float ptf = fmaxf(pt, 1e-8f);
        const float om  = 1.f - ptf;
        afoc  = fmaf(at * om * om, log_pt, afoc);          // negate at end

#pragma unroll
        for (int c = 0; c < NCLS; ++c) ps[c] = fmaf(e[c], invS, ps[c]);
#pragma unroll
        for (int c = 0; c < NCLS; ++c) {
            const bool p = (t == c);
            inter[c] += p ? pt : 0.f;
            cnt[c]   += p ? 1 : 0;
        }
    }

    // ---- Block reduction: warp shuffles, then smem atomics (once per block) ----
    const unsigned full = 0xffffffffu;
    const bool lead = ((tid & 31) == 0);
#pragma unroll
    for (int c = 0; c < NCLS; ++c) {
        float v0 = ps[c], v1 = inter[c], v2 = (float)cnt[c];
#pragma unroll
        for (int o = 16; o > 0; o >>= 1) {
            v0 += __shfl_down_sync(full, v0, o);
            v1 += __shfl_down_sync(full, v1, o);
            v2 += __shfl_down_sync(full, v2, o);
        }
        if (lead) {
            atomicAdd(&s_red[c], v0);
            atomicAdd(&s_red[NCLS + c], v1);
            atomicAdd(&s_red[2 * NCLS + c], v2);
        }
    }
    {
        float v0 = aw, v1 = anll, v2 = afoc;
#pragma unroll
        for (int o = 16; o > 0; o >>= 1) {
            v0 += __shfl_down_sync(full, v0, o);
            v1 += __shfl_down_sync(full, v1, o);
            v2 += __shfl_down_sync(full, v2, o);
        }
        if (lead) {
            atomicAdd(&s_red[57], v0);
            atomicAdd(&s_red[58], v1);
            atomicAdd(&s_red[59], v2);
        }
    }
    __syncthreads();

    if (tid < 64) g_part[blockIdx.x][tid] = s_red[tid];

    // ---- Last block performs the final reduction (deterministic order) ----
    __threadfence();
    if (tid == 0) s_last = (atomicAdd(&g_sem, 1u) == NBLK - 1);
    __syncthreads();
    if (!s_last) return;

    if (tid == 0) g_sem = 0;    // reset for next graph replay
    __threadfence();

    {
        const int v = tid & 63;
        const int slice = tid >> 6;          // 0..3
        float acc = 0.f;
        for (int bb = slice; bb < NBLK; bb += 4) acc += g_part[bb][v];
        s_fin[slice][v] = acc;
    }
    __syncthreads();
    if (tid < 64)
        s_fin[0][tid] = s_fin[0][tid] + s_fin[1][tid] + s_fin[2][tid] + s_fin[3][tid];
    __syncthreads();

    if (tid == 0) {
        const float ce    = -s_fin[0][58] / s_fin[0][57];
        const float focal = -s_fin[0][59] / (float)P;

        float sw = 0.f;
#pragma unroll
        for (int c = 0; c < NCLS; ++c) sw += s_cw[c];
        sw = fmaxf(sw, 1e-8f);

        float dsum = 0.f;
#pragma unroll
        for (int c = 0; c < NCLS; ++c) {
            const float dice = (2.f * s_fin[0][NCLS + c] + 1.f)
                             / (s_fin[0][c] + s_fin[0][2 * NCLS + c] + 1.f);
            dsum += dice * (s_cw[c] / sw);
        }
        const float dice_loss = 1.f - dsum;
        out[0] = 0.4f * ce + 0.3f * focal + 0.3f * dice_loss;
    }
}

extern "C" void kernel_launch(void* const* d_in, const int* in_sizes, int n_in,
                              void* d_out, int out_size)
{
    const float* logits = (const float*)d_in[0];
    const int*   target = (const int*)d_in[1];
    const float* cw     = (const float*)d_in[2];
    const float* fa     = (const float*)d_in[3];
    float*       out    = (float*)d_out;

    const int P = in_sizes[1];   // B*H*W = 2,097,152

    fdl_kernel<<<NBLK, NTHR>>>(logits, target, cw, fa, out, P);
}

// round 4
// speedup vs baseline: 1.2643x; 1.2643x over previous
#include <cuda_runtime.h>

// Fixed-shape problem: logits [8,19,512,512] f32, target [8,512,512] (int32 on device)
#define NCLS 19
#define HW   262144           // 512*512
#define HW4  65536            // HW/4
#define CHW  (NCLS * HW)
#define NBLK 148              // 1 CTA per SM, one wave
#define NTHR 256

// Per-block partials: [0..18]=prob_sums, [19..37]=intersection, [38..56]=counts,
// [57]=sum w_t, [58]=sum w_t*log_pt, [59]=sum alpha*(1-pt)^2*log_pt
__device__ float    g_part[NBLK][64];
__device__ unsigned g_sem;     // zero-initialized; self-resetting

__device__ __forceinline__ float ex2f(float x){ float r; asm("ex2.approx.ftz.f32 %0,%1;":"=f"(r):"f"(x)); return r; }
__device__ __forceinline__ float lg2f(float x){ float r; asm("lg2.approx.ftz.f32 %0,%1;":"=f"(r):"f"(x)); return r; }
__device__ __forceinline__ float rcpf(float x){ float r; asm("rcp.approx.ftz.f32 %0,%1;":"=f"(r):"f"(x)); return r; }

#define L2E 1.44269504088896f
#define LN2 0.69314718055995f

__global__ void __launch_bounds__(NTHR, 1)
fdl_kernel(const float* __restrict__ logits,
           const int*   __restrict__ target,
           const float* __restrict__ cw,
           const float* __restrict__ fa,
           float*       __restrict__ out,
           int P4)
{
    __shared__ float s_cw[NCLS], s_fa[NCLS];
    __shared__ float s_red[64];
    __shared__ float s_fin[4][64];
    __shared__ bool  s_last;

    const int tid = threadIdx.x;
    if (tid < NCLS) { s_cw[tid] = cw[tid]; s_fa[tid] = fa[tid]; }
    if (tid < 64)   s_red[tid] = 0.f;
    __syncthreads();

    // Per-thread accumulators (register-resident, static indexing only)
    float ps[NCLS], inter[NCLS];
    unsigned cntp[(NCLS + 1) / 2];          // two u16 counts per reg
#pragma unroll
    for (int c = 0; c < NCLS; ++c) { ps[c] = 0.f; inter[c] = 0.f; }
#pragma unroll
    for (int c = 0; c < (NCLS + 1) / 2; ++c) cntp[c] = 0u;
    float aw = 0.f, anll = 0.f, afoc = 0.f;

    const int stride = NBLK * NTHR;
    for (int pix4 = blockIdx.x * NTHR + tid; pix4 < P4; pix4 += stride) {
        const int b   = pix4 >> 16;          // pix4 / HW4
        const int hw4 = pix4 & (HW4 - 1);
        const float4* base = (const float4*)(logits + (size_t)b * CHW) + hw4;

        // 19 vectorized class streams: 19 x LDG.128 in flight per thread
        float4 l[NCLS];
#pragma unroll
        for (int c = 0; c < NCLS; ++c)
            l[c] = __ldg(base + (size_t)c * HW4);

        const int4 t4 = __ldg((const int4*)target + pix4);

        // Process the 4 sub-pixels; e[] temporaries reuse registers across PROC
#define PROC(COMP, TT)                                                        \
        do {                                                                  \
            float e[NCLS];                                                    \
            float S = 0.f;                                                    \
            _Pragma("unroll")                                                 \
            for (int c = 0; c < NCLS; ++c) {                                  \
                e[c] = ex2f(l[c].COMP * L2E);                                 \
                S += e[c];                                                    \
            }                                                                 \
            float yt = l[0].COMP;                                             \
            _Pragma("unroll")                                                 \
            for (int c = 1; c < NCLS; ++c) yt = ((TT) == c) ? l[c].COMP : yt; \
            const float invS = rcpf(S);                                       \
            const float d    = yt * L2E - lg2f(S);   /* log2(p_t) */          \
            const float log_pt = d * LN2;                                     \
            const float pt     = ex2f(d);                                     \
            const float wt = s_cw[TT];                                        \
            const float at = s_fa[TT];                                        \
            aw  += wt;                                                        \
            anll = fmaf(wt, log_pt, anll);                                    \
            const float ptf = fmaxf(pt, 1e-8f);                               \
            const float om  = 1.f - ptf;                                      \
            afoc = fmaf(at * om * om, log_pt, afoc);                          \
            _Pragma("unroll")                                                 \
            for (int c = 0; c < NCLS; ++c) {                                  \
                const bool p = ((TT) == c);                                   \
                ps[c]    = fmaf(e[c], invS, ps[c]);                           \
                inter[c] += p ? pt : 0.f;                                     \
                cntp[c >> 1] += p ? (1u << ((c & 1) * 16)) : 0u;              \
            }                                                                 \
        } while (0)

        PROC(x, t4.x);
        PROC(y, t4.y);
        PROC(z, t4.z);
        PROC(w, t4.w);
#undef PROC
    }

    // ---- Block reduction: warp shuffles, then smem atomics (once per block) ----
    const unsigned full = 0xffffffffu;
    const bool lead = ((tid & 31) == 0);
#pragma unroll
    for (int c = 0; c < NCLS; ++c) {
        const unsigned cc = cntp[c >> 1];
        float v0 = ps[c], v1 = inter[c];
        float v2 = (float)((c & 1) ? (cc >> 16) : (cc & 0xffffu));
#pragma unroll
        for (int o = 16; o > 0; o >>= 1) {
            v0 += __shfl_down_sync(full, v0, o);
            v1 += __shfl_down_sync(full, v1, o);
            v2 += __shfl_down_sync(full, v2, o);
        }
        if (lead) {
            atomicAdd(&s_red[c], v0);
            atomicAdd(&s_red[NCLS + c], v1);
            atomicAdd(&s_red[2 * NCLS + c], v2);
        }
    }
    {
        float v0 = aw, v1 = anll, v2 = afoc;
#pragma unroll
        for (int o = 16; o > 0; o >>= 1) {
            v0 += __shfl_down_sync(full, v0, o);
            v1 += __shfl_down_sync(full, v1, o);
            v2 += __shfl_down_sync(full, v2, o);
        }
        if (lead) {
            atomicAdd(&s_red[57], v0);
            atomicAdd(&s_red[58], v1);
            atomicAdd(&s_red[59], v2);
        }
    }
    __syncthreads();

    if (tid < 64) g_part[blockIdx.x][tid] = s_red[tid];

    // ---- Last block performs the final reduction (deterministic order) ----
    __threadfence();
    if (tid == 0) s_last = (atomicAdd(&g_sem, 1u) == NBLK - 1);
    __syncthreads();
    if (!s_last) return;

    if (tid == 0) g_sem = 0;    // reset for next graph replay
    __threadfence();

    {
        const int v = tid & 63;
        const int slice = tid >> 6;          // 0..3
        float acc = 0.f;
        for (int bb = slice; bb < NBLK; bb += 4) acc += g_part[bb][v];
        s_fin[slice][v] = acc;
    }
    __syncthreads();
    if (tid < 64)
        s_fin[0][tid] = s_fin[0][tid] + s_fin[1][tid] + s_fin[2][tid] + s_fin[3][tid];
    __syncthreads();

    if (tid == 0) {
        const float Pf    = (float)P4 * 4.0f;
        const float ce    = -s_fin[0][58] / s_fin[0][57];
        const float focal = -s_fin[0][59] / Pf;

        float sw = 0.f;
#pragma unroll
        for (int c = 0; c < NCLS; ++c) sw += s_cw[c];
        sw = fmaxf(sw, 1e-8f);

        float dsum = 0.f;
#pragma unroll
        for (int c = 0; c < NCLS; ++c) {
            const float dice = (2.f * s_fin[0][NCLS + c] + 1.f)
                             / (s_fin[0][c] + s_fin[0][2 * NCLS + c] + 1.f);
            dsum += dice * (s_cw[c] / sw);
        }
        const float dice_loss = 1.f - dsum;
        out[0] = 0.4f * ce + 0.3f * focal + 0.3f * dice_loss;
    }
}

extern "C" void kernel_launch(void* const* d_in, const int* in_sizes, int n_in,
                              void* d_out, int out_size)
{
    const float* logits = (const float*)d_in[0];
    const int*   target = (const int*)d_in[1];
    const float* cw     = (const float*)d_in[2];
    const float* fa     = (const float*)d_in[3];
    float*       out    = (float*)d_out;

    const int P4 = in_sizes[1] / 4;   // (B*H*W)/4 = 524,288

    fdl_kernel<<<NBLK, NTHR>>>(logits, target, cw, fa, out, P4);
}